// round 15
// baseline (speedup 1.0000x reference)
#include <cuda_runtime.h>
#include <cuda_fp16.h>
#include <cstdint>
#include <cstddef>

// Problem constants
#define NN 16384
#define EE 8192
#define FF 64
#define SPLIT 8
#define KSPLIT2 4
static_assert(NN % 128 == 0 && EE % 128 == 0, "tiling");

// ---------------- scratch (device globals; no cudaMalloc allowed) ----------------
__device__ __half g_Hh[(size_t)NN * EE];        // 256 MB fp16 copy of H
__device__ float  g_dv[NN];                     // rowsum^-0.5
__device__ float  g_departB[SPLIT * EE];        // per-split col sums (from gemm1)
__device__ __half g_u[(size_t)NN * FF];         // dv * (x@weight), fp16
__device__ __half g_tparth[SPLIT * EE * FF];    // split-k partials of H^T @ u (fp16, 8 MB)
__device__ __half g_t2[EE * FF];                // se * t, fp16
__device__ float  g_opart[(size_t)KSPLIT2 * NN * FF];  // split-k partials of H @ t2 (fp32, 16 MB)

#define OUT_SCALE 6.103515625e-05f  // 1/16384

// ---------------- PTX helpers ----------------
__device__ __forceinline__ void cp16(void* dst, const void* src) {
    uint32_t d = (uint32_t)__cvta_generic_to_shared(dst);
    asm volatile("cp.async.cg.shared.global [%0], [%1], 16;\n" :: "r"(d), "l"(src));
}
__device__ __forceinline__ void cp_commit() { asm volatile("cp.async.commit_group;\n"); }
template <int n>
__device__ __forceinline__ void cp_wait() { asm volatile("cp.async.wait_group %0;\n" :: "n"(n)); }

__device__ __forceinline__ void ldsm4(uint32_t (&r)[4], const void* p) {
    uint32_t a = (uint32_t)__cvta_generic_to_shared(p);
    asm volatile("ldmatrix.sync.aligned.m8n8.x4.shared.b16 {%0,%1,%2,%3}, [%4];"
                 : "=r"(r[0]), "=r"(r[1]), "=r"(r[2]), "=r"(r[3]) : "r"(a));
}
__device__ __forceinline__ void ldsm4t(uint32_t (&r)[4], const void* p) {
    uint32_t a = (uint32_t)__cvta_generic_to_shared(p);
    asm volatile("ldmatrix.sync.aligned.m8n8.x4.trans.shared.b16 {%0,%1,%2,%3}, [%4];"
                 : "=r"(r[0]), "=r"(r[1]), "=r"(r[2]), "=r"(r[3]) : "r"(a));
}
__device__ __forceinline__ void mma16816(float (&c)[4], const uint32_t (&a)[4],
                                         uint32_t b0, uint32_t b1) {
    asm volatile(
        "mma.sync.aligned.m16n8k16.row.col.f32.f16.f16.f32 "
        "{%0,%1,%2,%3},{%4,%5,%6,%7},{%8,%9},{%0,%1,%2,%3};"
        : "+f"(c[0]), "+f"(c[1]), "+f"(c[2]), "+f"(c[3])
        : "r"(a[0]), "r"(a[1]), "r"(a[2]), "r"(a[3]), "r"(b0), "r"(b1));
}
__device__ __forceinline__ uint32_t h2u(__half2 h) {
    return *reinterpret_cast<uint32_t*>(&h);
}

// ---------------- P0 fused: convert H->fp16 + row sums + u = dv*(x@weight) ----------------
// Monolithic: grid 2048 x 256 threads; warp owns one row (16384 rows total).
__global__ __launch_bounds__(256) void k_p0f(const float* __restrict__ H,
                                             const float* __restrict__ x,
                                             const float* __restrict__ w) {
    __shared__ float s_w[64][66];  // [k][f], pad 66 -> conflict-free column reads
    const int t = threadIdx.x;
    const int lane = t & 31;
    const int wid = t >> 5;
    for (int i = t; i < 4096; i += 256) s_w[i >> 6][i & 63] = w[i];

    const int row = blockIdx.x * 8 + wid;
    float2 xv = *(const float2*)&x[(size_t)row * 64 + 2 * lane];
    __syncthreads();

    const float4* __restrict__ src = (const float4*)(H + (size_t)row * EE);
    uint4* __restrict__ dst = (uint4*)(g_Hh + (size_t)row * EE);
    float s = 0.f;
#pragma unroll 2
    for (int j = 0; j < 16; j++) {
        const int base = j * 128;
        float4 v0 = src[base + 2 * lane];
        float4 v1 = src[base + 2 * lane + 1];
        float4 v2 = src[base + 64 + 2 * lane];
        float4 v3 = src[base + 64 + 2 * lane + 1];
        uint4 u0, u1;
        u0.x = h2u(__floats2half2_rn(v0.x, v0.y));
        u0.y = h2u(__floats2half2_rn(v0.z, v0.w));
        u0.z = h2u(__floats2half2_rn(v1.x, v1.y));
        u0.w = h2u(__floats2half2_rn(v1.z, v1.w));
        u1.x = h2u(__floats2half2_rn(v2.x, v2.y));
        u1.y = h2u(__floats2half2_rn(v2.z, v2.w));
        u1.z = h2u(__floats2half2_rn(v3.x, v3.y));
        u1.w = h2u(__floats2half2_rn(v3.z, v3.w));
        dst[j * 64 + lane] = u0;
        dst[j * 64 + 32 + lane] = u1;
        s += ((v0.x + v0.y) + (v0.z + v0.w)) + ((v1.x + v1.y) + (v1.z + v1.w)) +
             ((v2.x + v2.y) + (v2.z + v2.w)) + ((v3.x + v3.y) + (v3.z + v3.w));
    }
#pragma unroll
    for (int o = 16; o; o >>= 1) s += __shfl_xor_sync(0xffffffffu, s, o);
    float dvn = rsqrtf(s);
    if (lane == 0) g_dv[row] = dvn;

    float a0 = 0.f, a1 = 0.f;
#pragma unroll
    for (int k = 0; k < 64; k++) {
        float xk = __shfl_sync(0xffffffffu, (k & 1) ? xv.y : xv.x, k >> 1);
        a0 += xk * s_w[k][lane];
        a1 += xk * s_w[k][lane + 32];
    }
    g_u[(size_t)row * 64 + lane] = __float2half_rn(dvn * a0);
    g_u[(size_t)row * 64 + lane + 32] = __float2half_rn(dvn * a1);
}

// ---------------- GEMM1: tpart[split] = H^T @ u over 1/SPLIT of n, plus col sums ----------------
// grid (EE/128, SPLIT) = (64, 8) = 512 CTAs; launch_bounds(256,4) -> 4 CTAs/SM, single wave.
// BM=128 (e), BN=64 (f), BK=32 (n), 3-stage.
#define G1_STAGES 3
__global__ __launch_bounds__(256, 4) void k_gemm1() {
    __shared__ __half sA[G1_STAGES][32][136];  // [k=n][m=e], stride 272B == 16 mod 128
    __shared__ __half sB[G1_STAGES][32][72];   // [k=n][f],  stride 144B == 16 mod 128
    __shared__ float2 s_red[256];
    const int t = threadIdx.x;
    const int lane = t & 31;
    const int wid = t >> 5;
    const int mb = (wid >> 1) * 32;
    const int nb = (wid & 1) * 32;
    const int e0 = blockIdx.x * 128;
    const size_t kbase = (size_t)blockIdx.y * (NN / SPLIT);
    float c[2][4][4];
#pragma unroll
    for (int i = 0; i < 2; i++)
#pragma unroll
        for (int j = 0; j < 4; j++)
#pragma unroll
            for (int k = 0; k < 4; k++) c[i][j][k] = 0.f;

    const int br = t >> 3, bc = (t & 7) * 8;
    const int cp2 = (t & 63) * 2;
    const int kr0 = (t >> 6) * 8;
    float csx = 0.f, csy = 0.f;

    const int ITERS = (NN / SPLIT) / 32;  // 64

#pragma unroll
    for (int s = 0; s < G1_STAGES - 1; s++) {
        size_t k0 = kbase + (size_t)s * 32;
#pragma unroll
        for (int i = 0; i < 2; i++) {
            int q = t + 256 * i, row = q >> 4, co = (q & 15) * 8;
            cp16(&sA[s][row][co], g_Hh + (k0 + row) * (size_t)EE + e0 + co);
        }
        cp16(&sB[s][br][bc], g_u + (k0 + br) * 64 + bc);
        cp_commit();
    }

    for (int it = 0; it < ITERS; ++it) {
        cp_wait<G1_STAGES - 2>();
        __syncthreads();
        const int cur = it % G1_STAGES;
        if (it + G1_STAGES - 1 < ITERS) {
            const int nxt = (it + G1_STAGES - 1) % G1_STAGES;
            size_t k0 = kbase + (size_t)(it + G1_STAGES - 1) * 32;
#pragma unroll
            for (int i = 0; i < 2; i++) {
                int q = t + 256 * i, row = q >> 4, co = (q & 15) * 8;
                cp16(&sA[nxt][row][co], g_Hh + (k0 + row) * (size_t)EE + e0 + co);
            }
            cp16(&sB[nxt][br][bc], g_u + (k0 + br) * 64 + bc);
        }
        cp_commit();
#pragma unroll
        for (int ks = 0; ks < 2; ks++) {
            const int kb = ks * 16;
            uint32_t a[2][4], b[2][4];
            {
                int krow = kb + (lane & 7) + ((lane & 16) ? 8 : 0);
                int mc0 = mb + ((lane & 8) ? 8 : 0);
                ldsm4t(a[0], &sA[cur][krow][mc0]);
                ldsm4t(a[1], &sA[cur][krow][mc0 + 16]);
            }
            {
                int krow = kb + (lane & 7) + (lane & 8);
                int nc0 = nb + ((lane & 16) ? 8 : 0);
                ldsm4t(b[0], &sB[cur][krow][nc0]);
                ldsm4t(b[1], &sB[cur][krow][nc0 + 16]);
            }
#pragma unroll
            for (int mi = 0; mi < 2; mi++)
#pragma unroll
                for (int nj = 0; nj < 2; nj++) {
                    mma16816(c[mi][2 * nj], a[mi], b[nj][0], b[nj][1]);
                    mma16816(c[mi][2 * nj + 1], a[mi], b[nj][2], b[nj][3]);
                }
        }
#pragma unroll
        for (int kk = 0; kk < 8; kk++) {
            __half2 v = *(const __half2*)&sA[cur][kr0 + kk][cp2];
            float2 f = __half22float2(v);
            csx += f.x;
            csy += f.y;
        }
    }

    s_red[t] = make_float2(csx, csy);
    __syncthreads();
    if (t < 64) {
        float2 a0 = s_red[t], a1 = s_red[t + 64], a2 = s_red[t + 128], a3 = s_red[t + 192];
        float2 r = make_float2(a0.x + a1.x + a2.x + a3.x, a0.y + a1.y + a2.y + a3.y);
        *(float2*)&g_departB[(size_t)blockIdx.y * EE + e0 + 2 * t] = r;
    }

    const int g = lane >> 2, tig = lane & 3;
    __half* op = g_tparth + (size_t)blockIdx.y * (EE * 64);
#pragma unroll
    for (int mi = 0; mi < 2; mi++) {
        int e = e0 + mb + mi * 16 + g;
#pragma unroll
        for (int nt = 0; nt < 4; nt++) {
            int f = nb + nt * 8 + 2 * tig;
            *(__half2*)&op[(size_t)e * 64 + f] = __floats2half2_rn(c[mi][nt][0], c[mi][nt][1]);
            *(__half2*)&op[(size_t)(e + 8) * 64 + f] = __floats2half2_rn(c[mi][nt][2], c[mi][nt][3]);
        }
    }
}

// ---------------- P3: t2 = fp16( se[e] * sum_s tpart[s] ),  se = W*2^14/colsum ----------------
__global__ __launch_bounds__(256) void k_combine(const float* __restrict__ W) {
    int idx = blockIdx.x * 256 + threadIdx.x;  // uint2 (4-half) index, 0 .. EE*16-1
    int e = idx >> 4;
    float cs = 0.f;
#pragma unroll
    for (int s = 0; s < SPLIT; s++) cs += g_departB[(size_t)s * EE + e];
    float se = W[e] * 16384.0f / cs;
    const uint2* tp = (const uint2*)g_tparth;
    float ax = 0.f, ay = 0.f, az = 0.f, aw = 0.f;
#pragma unroll
    for (int s = 0; s < SPLIT; s++) {
        uint2 v = tp[(size_t)s * (EE * 16) + idx];
        float2 f0 = __half22float2(*reinterpret_cast<__half2*>(&v.x));
        float2 f1 = __half22float2(*reinterpret_cast<__half2*>(&v.y));
        ax += f0.x; ay += f0.y; az += f1.x; aw += f1.y;
    }
    uint2 uu;
    uu.x = h2u(__floats2half2_rn(se * ax, se * ay));
    uu.y = h2u(__floats2half2_rn(se * az, se * aw));
    ((uint2*)g_t2)[idx] = uu;
}

// ---------------- GEMM2: opart[split] = H @ t2 over 1/KSPLIT2 of e ----------------
// grid (NN/128, KSPLIT2) = (128, 4) = 512 CTAs, single wave at 4/SM;
// 256 threads (8 warps: 4m x 2n, 32x32 warp tiles); BM=128, BN=64, BK=32, 3-stage.
#define G2_STAGES 3
__global__ __launch_bounds__(256, 4) void k_gemm2() {
    __shared__ __half sA[G2_STAGES][128][40];  // [m=n][k=e], stride 80B
    __shared__ __half sB[G2_STAGES][32][72];   // [k=e][f]
    const int t = threadIdx.x;
    const int lane = t & 31;
    const int wid = t >> 5;
    const int mb = (wid >> 1) * 32;   // 4 m-warps
    const int nb = (wid & 1) * 32;    // 2 n-warps
    const int m0 = blockIdx.x * 128;
    const size_t kbase = (size_t)blockIdx.y * (EE / KSPLIT2);
    float c[2][4][4];
#pragma unroll
    for (int i = 0; i < 2; i++)
#pragma unroll
        for (int j = 0; j < 4; j++)
#pragma unroll
            for (int k = 0; k < 4; k++) c[i][j][k] = 0.f;

    const int br = t >> 3, bc = (t & 7) * 8;
    const int ITERS = (EE / KSPLIT2) / 32;  // 64

#pragma unroll
    for (int s = 0; s < G2_STAGES - 1; s++) {
        size_t k0 = kbase + (size_t)s * 32;
#pragma unroll
        for (int i = 0; i < 2; i++) {
            int q = t + 256 * i, row = q >> 2, co = (q & 3) * 8;
            cp16(&sA[s][row][co], g_Hh + (size_t)(m0 + row) * EE + k0 + co);
        }
        cp16(&sB[s][br][bc], g_t2 + (k0 + br) * 64 + bc);
        cp_commit();
    }

    for (int it = 0; it < ITERS; ++it) {
        cp_wait<G2_STAGES - 2>();
        __syncthreads();
        const int cur = it % G2_STAGES;
        if (it + G2_STAGES - 1 < ITERS) {
            const int nxt = (it + G2_STAGES - 1) % G2_STAGES;
            size_t k0 = kbase + (size_t)(it + G2_STAGES - 1) * 32;
#pragma unroll
            for (int i = 0; i < 2; i++) {
                int q = t + 256 * i, row = q >> 2, co = (q & 3) * 8;
                cp16(&sA[nxt][row][co], g_Hh + (size_t)(m0 + row) * EE + k0 + co);
            }
            cp16(&sB[nxt][br][bc], g_t2 + (k0 + br) * 64 + bc);
        }
        cp_commit();
#pragma unroll
        for (int ks = 0; ks < 2; ks++) {
            const int kb = ks * 16;
            uint32_t a[2][4], b[2][4];
            {
                int arow = mb + (lane & 15);
                int kc = kb + ((lane & 16) ? 8 : 0);
                ldsm4(a[0], &sA[cur][arow][kc]);
                ldsm4(a[1], &sA[cur][arow + 16][kc]);
            }
            {
                int krow = kb + (lane & 7) + (lane & 8);
                int nc0 = nb + ((lane & 16) ? 8 : 0);
                ldsm4t(b[0], &sB[cur][krow][nc0]);
                ldsm4t(b[1], &sB[cur][krow][nc0 + 16]);
            }
#pragma unroll
            for (int mi = 0; mi < 2; mi++)
#pragma unroll
                for (int nj = 0; nj < 2; nj++) {
                    mma16816(c[mi][2 * nj], a[mi], b[nj][0], b[nj][1]);
                    mma16816(c[mi][2 * nj + 1], a[mi], b[nj][2], b[nj][3]);
                }
        }
    }

    const int g = lane >> 2, tig = lane & 3;
    float* op = g_opart + (size_t)blockIdx.y * ((size_t)NN * 64);
#pragma unroll
    for (int mi = 0; mi < 2; mi++) {
        int n = m0 + mb + mi * 16 + g;
#pragma unroll
        for (int nt = 0; nt < 4; nt++) {
            int f = nb + nt * 8 + 2 * tig;
            *(float2*)&op[(size_t)n * 64 + f] = make_float2(c[mi][nt][0], c[mi][nt][1]);
            *(float2*)&op[(size_t)(n + 8) * 64 + f] = make_float2(c[mi][nt][2], c[mi][nt][3]);
        }
    }
}

// ---------------- Epilogue: out = dv * (sum of partials) / 2^14 + bias ----------------
__global__ __launch_bounds__(256) void k_epi(const float* __restrict__ bias,
                                             float* __restrict__ out) {
    int idx = blockIdx.x * 256 + threadIdx.x;  // float4 index, 0 .. NN*16-1
    int n = idx >> 4;
    float dvn = g_dv[n] * OUT_SCALE;
    const float4* p = (const float4*)g_opart;
    float ax = 0.f, ay = 0.f, az = 0.f, aw = 0.f;
#pragma unroll
    for (int s = 0; s < KSPLIT2; s++) {
        float4 v = p[(size_t)s * (NN * 16) + idx];
        ax += v.x; ay += v.y; az += v.z; aw += v.w;
    }
    int f = (idx & 15) * 4;
    float4 r;
    r.x = dvn * ax + bias[f];
    r.y = dvn * ay + bias[f + 1];
    r.z = dvn * az + bias[f + 2];
    r.w = dvn * aw + bias[f + 3];
    ((float4*)out)[idx] = r;
}

// ---------------- launch ----------------
extern "C" void kernel_launch(void* const* d_in, const int* in_sizes, int n_in,
                              void* d_out, int out_size) {
    (void)in_sizes; (void)n_in; (void)out_size;
    const float* x = (const float*)d_in[0];       // [N,64]
    const float* H = (const float*)d_in[1];       // [N,E]
    const float* W = (const float*)d_in[2];       // [E]
    const float* w = (const float*)d_in[3];       // [64,64]
    const float* b = (const float*)d_in[4];       // [64]
    float* out = (float*)d_out;                   // [N,64]

    k_p0f<<<2048, 256>>>(H, x, w);
    k_gemm1<<<dim3(64, SPLIT), 256>>>();
    k_combine<<<512, 256>>>(W);
    k_gemm2<<<dim3(128, KSPLIT2), 256>>>();
    k_epi<<<1024, 256>>>(b, out);
}

// round 16
// speedup vs baseline: 1.0461x; 1.0461x over previous
#include <cuda_runtime.h>
#include <cuda_fp16.h>
#include <cstdint>
#include <cstddef>

// Problem constants
#define NN 16384
#define EE 8192
#define FF 64
#define SPLIT 8
#define KSPLIT2 8
static_assert(NN % 128 == 0 && EE % 128 == 0, "tiling");

// ---------------- scratch (device globals; no cudaMalloc allowed) ----------------
__device__ __half g_Hh[(size_t)NN * EE];        // 256 MB fp16 copy of H
__device__ float  g_dv[NN];                     // rowsum^-0.5
__device__ float  g_departB[SPLIT * EE];        // per-split col sums (from gemm1)
__device__ __half g_u[(size_t)NN * FF];         // dv * (x@weight), fp16
__device__ __half g_tparth[SPLIT * EE * FF];    // split-k partials of H^T @ u (fp16, 8 MB)
__device__ __half g_t2[EE * FF];                // se * t, fp16
__device__ float  g_opart[(size_t)KSPLIT2 * NN * FF];  // split-k partials of H @ t2 (fp32, 32 MB)

#define OUT_SCALE 6.103515625e-05f  // 1/16384

// ---------------- PTX helpers ----------------
__device__ __forceinline__ void cp16(void* dst, const void* src) {
    uint32_t d = (uint32_t)__cvta_generic_to_shared(dst);
    asm volatile("cp.async.cg.shared.global [%0], [%1], 16;\n" :: "r"(d), "l"(src));
}
__device__ __forceinline__ void cp_commit() { asm volatile("cp.async.commit_group;\n"); }
template <int n>
__device__ __forceinline__ void cp_wait() { asm volatile("cp.async.wait_group %0;\n" :: "n"(n)); }

__device__ __forceinline__ void ldsm4(uint32_t (&r)[4], const void* p) {
    uint32_t a = (uint32_t)__cvta_generic_to_shared(p);
    asm volatile("ldmatrix.sync.aligned.m8n8.x4.shared.b16 {%0,%1,%2,%3}, [%4];"
                 : "=r"(r[0]), "=r"(r[1]), "=r"(r[2]), "=r"(r[3]) : "r"(a));
}
__device__ __forceinline__ void ldsm4t(uint32_t (&r)[4], const void* p) {
    uint32_t a = (uint32_t)__cvta_generic_to_shared(p);
    asm volatile("ldmatrix.sync.aligned.m8n8.x4.trans.shared.b16 {%0,%1,%2,%3}, [%4];"
                 : "=r"(r[0]), "=r"(r[1]), "=r"(r[2]), "=r"(r[3]) : "r"(a));
}
__device__ __forceinline__ void mma16816(float (&c)[4], const uint32_t (&a)[4],
                                         uint32_t b0, uint32_t b1) {
    asm volatile(
        "mma.sync.aligned.m16n8k16.row.col.f32.f16.f16.f32 "
        "{%0,%1,%2,%3},{%4,%5,%6,%7},{%8,%9},{%0,%1,%2,%3};"
        : "+f"(c[0]), "+f"(c[1]), "+f"(c[2]), "+f"(c[3])
        : "r"(a[0]), "r"(a[1]), "r"(a[2]), "r"(a[3]), "r"(b0), "r"(b1));
}
__device__ __forceinline__ uint32_t h2u(__half2 h) {
    return *reinterpret_cast<uint32_t*>(&h);
}

// ---------------- P0 fused: convert H->fp16 + row sums + u = dv*(x@weight) ----------------
// Monolithic: grid 2048 x 256 threads; warp owns one row; 8 LDG.128 in flight per iter.
__global__ __launch_bounds__(256) void k_p0f(const float* __restrict__ H,
                                             const float* __restrict__ x,
                                             const float* __restrict__ w) {
    __shared__ float s_w[64][66];  // [k][f], pad 66 -> conflict-free column reads
    const int t = threadIdx.x;
    const int lane = t & 31;
    const int wid = t >> 5;
    for (int i = t; i < 4096; i += 256) s_w[i >> 6][i & 63] = w[i];

    const int row = blockIdx.x * 8 + wid;
    float2 xv = *(const float2*)&x[(size_t)row * 64 + 2 * lane];
    __syncthreads();

    const float4* __restrict__ src = (const float4*)(H + (size_t)row * EE);
    uint4* __restrict__ dst = (uint4*)(g_Hh + (size_t)row * EE);
    float s = 0.f;
    for (int j = 0; j < 8; j++) {
        const int base = j * 256;  // float4 units
        float4 v[8];
        // 8 LDG.128 issued back-to-back (pairs contiguous per lane)
#pragma unroll
        for (int i = 0; i < 4; i++) {
            v[2 * i]     = src[base + i * 64 + 2 * lane];
            v[2 * i + 1] = src[base + i * 64 + 2 * lane + 1];
        }
#pragma unroll
        for (int i = 0; i < 4; i++) {
            float4 a = v[2 * i], b = v[2 * i + 1];
            uint4 uu;
            uu.x = h2u(__floats2half2_rn(a.x, a.y));
            uu.y = h2u(__floats2half2_rn(a.z, a.w));
            uu.z = h2u(__floats2half2_rn(b.x, b.y));
            uu.w = h2u(__floats2half2_rn(b.z, b.w));
            dst[j * 128 + i * 32 + lane] = uu;
            s += ((a.x + a.y) + (a.z + a.w)) + ((b.x + b.y) + (b.z + b.w));
        }
    }
#pragma unroll
    for (int o = 16; o; o >>= 1) s += __shfl_xor_sync(0xffffffffu, s, o);
    float dvn = rsqrtf(s);
    if (lane == 0) g_dv[row] = dvn;

    float a0 = 0.f, a1 = 0.f;
#pragma unroll
    for (int k = 0; k < 64; k++) {
        float xk = __shfl_sync(0xffffffffu, (k & 1) ? xv.y : xv.x, k >> 1);
        a0 += xk * s_w[k][lane];
        a1 += xk * s_w[k][lane + 32];
    }
    g_u[(size_t)row * 64 + lane] = __float2half_rn(dvn * a0);
    g_u[(size_t)row * 64 + lane + 32] = __float2half_rn(dvn * a1);
}

// ---------------- GEMM1: tpart[split] = H^T @ u over 1/SPLIT of n, plus col sums ----------------
// grid (EE/128, SPLIT) = (64, 8) = 512 CTAs; launch_bounds(256,4) -> 4 CTAs/SM.
// BM=128 (e), BN=64 (f), BK=32 (n), 3-stage.
#define G1_STAGES 3
__global__ __launch_bounds__(256, 4) void k_gemm1() {
    __shared__ __half sA[G1_STAGES][32][136];  // [k=n][m=e], stride 272B == 16 mod 128
    __shared__ __half sB[G1_STAGES][32][72];   // [k=n][f],  stride 144B == 16 mod 128
    __shared__ float2 s_red[256];
    const int t = threadIdx.x;
    const int lane = t & 31;
    const int wid = t >> 5;
    const int mb = (wid >> 1) * 32;
    const int nb = (wid & 1) * 32;
    const int e0 = blockIdx.x * 128;
    const size_t kbase = (size_t)blockIdx.y * (NN / SPLIT);
    float c[2][4][4];
#pragma unroll
    for (int i = 0; i < 2; i++)
#pragma unroll
        for (int j = 0; j < 4; j++)
#pragma unroll
            for (int k = 0; k < 4; k++) c[i][j][k] = 0.f;

    const int br = t >> 3, bc = (t & 7) * 8;
    const int cp2 = (t & 63) * 2;
    const int kr0 = (t >> 6) * 8;
    float csx = 0.f, csy = 0.f;

    const int ITERS = (NN / SPLIT) / 32;  // 64

#pragma unroll
    for (int s = 0; s < G1_STAGES - 1; s++) {
        size_t k0 = kbase + (size_t)s * 32;
#pragma unroll
        for (int i = 0; i < 2; i++) {
            int q = t + 256 * i, row = q >> 4, co = (q & 15) * 8;
            cp16(&sA[s][row][co], g_Hh + (k0 + row) * (size_t)EE + e0 + co);
        }
        cp16(&sB[s][br][bc], g_u + (k0 + br) * 64 + bc);
        cp_commit();
    }

    for (int it = 0; it < ITERS; ++it) {
        cp_wait<G1_STAGES - 2>();
        __syncthreads();
        const int cur = it % G1_STAGES;
        if (it + G1_STAGES - 1 < ITERS) {
            const int nxt = (it + G1_STAGES - 1) % G1_STAGES;
            size_t k0 = kbase + (size_t)(it + G1_STAGES - 1) * 32;
#pragma unroll
            for (int i = 0; i < 2; i++) {
                int q = t + 256 * i, row = q >> 4, co = (q & 15) * 8;
                cp16(&sA[nxt][row][co], g_Hh + (k0 + row) * (size_t)EE + e0 + co);
            }
            cp16(&sB[nxt][br][bc], g_u + (k0 + br) * 64 + bc);
        }
        cp_commit();
#pragma unroll
        for (int ks = 0; ks < 2; ks++) {
            const int kb = ks * 16;
            uint32_t a[2][4], b[2][4];
            {
                int krow = kb + (lane & 7) + ((lane & 16) ? 8 : 0);
                int mc0 = mb + ((lane & 8) ? 8 : 0);
                ldsm4t(a[0], &sA[cur][krow][mc0]);
                ldsm4t(a[1], &sA[cur][krow][mc0 + 16]);
            }
            {
                int krow = kb + (lane & 7) + (lane & 8);
                int nc0 = nb + ((lane & 16) ? 8 : 0);
                ldsm4t(b[0], &sB[cur][krow][nc0]);
                ldsm4t(b[1], &sB[cur][krow][nc0 + 16]);
            }
#pragma unroll
            for (int mi = 0; mi < 2; mi++)
#pragma unroll
                for (int nj = 0; nj < 2; nj++) {
                    mma16816(c[mi][2 * nj], a[mi], b[nj][0], b[nj][1]);
                    mma16816(c[mi][2 * nj + 1], a[mi], b[nj][2], b[nj][3]);
                }
        }
#pragma unroll
        for (int kk = 0; kk < 8; kk++) {
            __half2 v = *(const __half2*)&sA[cur][kr0 + kk][cp2];
            float2 f = __half22float2(v);
            csx += f.x;
            csy += f.y;
        }
    }

    s_red[t] = make_float2(csx, csy);
    __syncthreads();
    if (t < 64) {
        float2 a0 = s_red[t], a1 = s_red[t + 64], a2 = s_red[t + 128], a3 = s_red[t + 192];
        float2 r = make_float2(a0.x + a1.x + a2.x + a3.x, a0.y + a1.y + a2.y + a3.y);
        *(float2*)&g_departB[(size_t)blockIdx.y * EE + e0 + 2 * t] = r;
    }

    const int g = lane >> 2, tig = lane & 3;
    __half* op = g_tparth + (size_t)blockIdx.y * (EE * 64);
#pragma unroll
    for (int mi = 0; mi < 2; mi++) {
        int e = e0 + mb + mi * 16 + g;
#pragma unroll
        for (int nt = 0; nt < 4; nt++) {
            int f = nb + nt * 8 + 2 * tig;
            *(__half2*)&op[(size_t)e * 64 + f] = __floats2half2_rn(c[mi][nt][0], c[mi][nt][1]);
            *(__half2*)&op[(size_t)(e + 8) * 64 + f] = __floats2half2_rn(c[mi][nt][2], c[mi][nt][3]);
        }
    }
}

// ---------------- P3: t2 = fp16( se[e] * sum_s tpart[s] ),  se = W*2^14/colsum ----------------
__global__ __launch_bounds__(256) void k_combine(const float* __restrict__ W) {
    int idx = blockIdx.x * 256 + threadIdx.x;  // uint2 (4-half) index, 0 .. EE*16-1
    int e = idx >> 4;
    float cs = 0.f;
#pragma unroll
    for (int s = 0; s < SPLIT; s++) cs += g_departB[(size_t)s * EE + e];
    float se = W[e] * 16384.0f / cs;
    const uint2* tp = (const uint2*)g_tparth;
    float ax = 0.f, ay = 0.f, az = 0.f, aw = 0.f;
#pragma unroll
    for (int s = 0; s < SPLIT; s++) {
        uint2 v = tp[(size_t)s * (EE * 16) + idx];
        float2 f0 = __half22float2(*reinterpret_cast<__half2*>(&v.x));
        float2 f1 = __half22float2(*reinterpret_cast<__half2*>(&v.y));
        ax += f0.x; ay += f0.y; az += f1.x; aw += f1.y;
    }
    uint2 uu;
    uu.x = h2u(__floats2half2_rn(se * ax, se * ay));
    uu.y = h2u(__floats2half2_rn(se * az, se * aw));
    ((uint2*)g_t2)[idx] = uu;
}

// ---------------- GEMM2: opart[split] = H @ t2 over 1/KSPLIT2 of e ----------------
// grid (NN/128, KSPLIT2) = (128, 8) = 1024 CTAs (R14 proven-best config);
// 256 threads (8 warps: 4m x 2n, 32x32 warp tiles); BM=128, BN=64, BK=32, 3-stage.
#define G2_STAGES 3
__global__ __launch_bounds__(256, 4) void k_gemm2() {
    __shared__ __half sA[G2_STAGES][128][40];  // [m=n][k=e], stride 80B
    __shared__ __half sB[G2_STAGES][32][72];   // [k=e][f]
    const int t = threadIdx.x;
    const int lane = t & 31;
    const int wid = t >> 5;
    const int mb = (wid >> 1) * 32;   // 4 m-warps
    const int nb = (wid & 1) * 32;    // 2 n-warps
    const int m0 = blockIdx.x * 128;
    const size_t kbase = (size_t)blockIdx.y * (EE / KSPLIT2);
    float c[2][4][4];
#pragma unroll
    for (int i = 0; i < 2; i++)
#pragma unroll
        for (int j = 0; j < 4; j++)
#pragma unroll
            for (int k = 0; k < 4; k++) c[i][j][k] = 0.f;

    const int br = t >> 3, bc = (t & 7) * 8;
    const int ITERS = (EE / KSPLIT2) / 32;  // 32

#pragma unroll
    for (int s = 0; s < G2_STAGES - 1; s++) {
        size_t k0 = kbase + (size_t)s * 32;
#pragma unroll
        for (int i = 0; i < 2; i++) {
            int q = t + 256 * i, row = q >> 2, co = (q & 3) * 8;
            cp16(&sA[s][row][co], g_Hh + (size_t)(m0 + row) * EE + k0 + co);
        }
        cp16(&sB[s][br][bc], g_t2 + (k0 + br) * 64 + bc);
        cp_commit();
    }

    for (int it = 0; it < ITERS; ++it) {
        cp_wait<G2_STAGES - 2>();
        __syncthreads();
        const int cur = it % G2_STAGES;
        if (it + G2_STAGES - 1 < ITERS) {
            const int nxt = (it + G2_STAGES - 1) % G2_STAGES;
            size_t k0 = kbase + (size_t)(it + G2_STAGES - 1) * 32;
#pragma unroll
            for (int i = 0; i < 2; i++) {
                int q = t + 256 * i, row = q >> 2, co = (q & 3) * 8;
                cp16(&sA[nxt][row][co], g_Hh + (size_t)(m0 + row) * EE + k0 + co);
            }
            cp16(&sB[nxt][br][bc], g_t2 + (k0 + br) * 64 + bc);
        }
        cp_commit();
#pragma unroll
        for (int ks = 0; ks < 2; ks++) {
            const int kb = ks * 16;
            uint32_t a[2][4], b[2][4];
            {
                int arow = mb + (lane & 15);
                int kc = kb + ((lane & 16) ? 8 : 0);
                ldsm4(a[0], &sA[cur][arow][kc]);
                ldsm4(a[1], &sA[cur][arow + 16][kc]);
            }
            {
                int krow = kb + (lane & 7) + (lane & 8);
                int nc0 = nb + ((lane & 16) ? 8 : 0);
                ldsm4t(b[0], &sB[cur][krow][nc0]);
                ldsm4t(b[1], &sB[cur][krow][nc0 + 16]);
            }
#pragma unroll
            for (int mi = 0; mi < 2; mi++)
#pragma unroll
                for (int nj = 0; nj < 2; nj++) {
                    mma16816(c[mi][2 * nj], a[mi], b[nj][0], b[nj][1]);
                    mma16816(c[mi][2 * nj + 1], a[mi], b[nj][2], b[nj][3]);
                }
        }
    }

    const int g = lane >> 2, tig = lane & 3;
    float* op = g_opart + (size_t)blockIdx.y * ((size_t)NN * 64);
#pragma unroll
    for (int mi = 0; mi < 2; mi++) {
        int n = m0 + mb + mi * 16 + g;
#pragma unroll
        for (int nt = 0; nt < 4; nt++) {
            int f = nb + nt * 8 + 2 * tig;
            *(float2*)&op[(size_t)n * 64 + f] = make_float2(c[mi][nt][0], c[mi][nt][1]);
            *(float2*)&op[(size_t)(n + 8) * 64 + f] = make_float2(c[mi][nt][2], c[mi][nt][3]);
        }
    }
}

// ---------------- Epilogue: out = dv * (sum of partials) / 2^14 + bias ----------------
__global__ __launch_bounds__(256) void k_epi(const float* __restrict__ bias,
                                             float* __restrict__ out) {
    int idx = blockIdx.x * 256 + threadIdx.x;  // float4 index, 0 .. NN*16-1
    int n = idx >> 4;
    float dvn = g_dv[n] * OUT_SCALE;
    const float4* p = (const float4*)g_opart;
    float ax = 0.f, ay = 0.f, az = 0.f, aw = 0.f;
#pragma unroll
    for (int s = 0; s < KSPLIT2; s++) {
        float4 v = p[(size_t)s * (NN * 16) + idx];
        ax += v.x; ay += v.y; az += v.z; aw += v.w;
    }
    int f = (idx & 15) * 4;
    float4 r;
    r.x = dvn * ax + bias[f];
    r.y = dvn * ay + bias[f + 1];
    r.z = dvn * az + bias[f + 2];
    r.w = dvn * aw + bias[f + 3];
    ((float4*)out)[idx] = r;
}

// ---------------- launch ----------------
extern "C" void kernel_launch(void* const* d_in, const int* in_sizes, int n_in,
                              void* d_out, int out_size) {
    (void)in_sizes; (void)n_in; (void)out_size;
    const float* x = (const float*)d_in[0];       // [N,64]
    const float* H = (const float*)d_in[1];       // [N,E]
    const float* W = (const float*)d_in[2];       // [E]
    const float* w = (const float*)d_in[3];       // [64,64]
    const float* b = (const float*)d_in[4];       // [64]
    float* out = (float*)d_out;                   // [N,64]

    k_p0f<<<2048, 256>>>(H, x, w);
    k_gemm1<<<dim3(64, SPLIT), 256>>>();
    k_combine<<<512, 256>>>(W);
    k_gemm2<<<dim3(128, KSPLIT2), 256>>>();
    k_epi<<<1024, 256>>>(b, out);
}

// round 17
// speedup vs baseline: 1.0555x; 1.0090x over previous
#include <cuda_runtime.h>
#include <cuda_fp16.h>
#include <cstdint>
#include <cstddef>

// Problem constants
#define NN 16384
#define EE 8192
#define FF 64
#define SPLIT 8
#define KSPLIT2 8
static_assert(NN % 128 == 0 && EE % 128 == 0, "tiling");

// ---------------- scratch (device globals; no cudaMalloc allowed) ----------------
__device__ __half g_Hh[(size_t)NN * EE];        // 256 MB fp16 copy of H
__device__ float  g_dv[NN];                     // rowsum^-0.5
__device__ float  g_departB[SPLIT * EE];        // per-split col sums (from gemm1)
__device__ __half g_u[(size_t)NN * FF];         // dv * (x@weight), fp16
__device__ __half g_tparth[SPLIT * EE * FF];    // split-k partials of H^T @ u (fp16, 8 MB)
__device__ __half g_t2[EE * FF];                // se * t, fp16
__device__ __half g_oparth[(size_t)KSPLIT2 * NN * FF];  // split-k partials of H @ t2 (fp16, 16 MB)

#define OUT_SCALE 6.103515625e-05f  // 1/16384

// ---------------- PTX helpers ----------------
__device__ __forceinline__ void cp16(void* dst, const void* src) {
    uint32_t d = (uint32_t)__cvta_generic_to_shared(dst);
    asm volatile("cp.async.cg.shared.global [%0], [%1], 16;\n" :: "r"(d), "l"(src));
}
__device__ __forceinline__ void cp_commit() { asm volatile("cp.async.commit_group;\n"); }
template <int n>
__device__ __forceinline__ void cp_wait() { asm volatile("cp.async.wait_group %0;\n" :: "n"(n)); }

__device__ __forceinline__ void ldsm4(uint32_t (&r)[4], const void* p) {
    uint32_t a = (uint32_t)__cvta_generic_to_shared(p);
    asm volatile("ldmatrix.sync.aligned.m8n8.x4.shared.b16 {%0,%1,%2,%3}, [%4];"
                 : "=r"(r[0]), "=r"(r[1]), "=r"(r[2]), "=r"(r[3]) : "r"(a));
}
__device__ __forceinline__ void ldsm4t(uint32_t (&r)[4], const void* p) {
    uint32_t a = (uint32_t)__cvta_generic_to_shared(p);
    asm volatile("ldmatrix.sync.aligned.m8n8.x4.trans.shared.b16 {%0,%1,%2,%3}, [%4];"
                 : "=r"(r[0]), "=r"(r[1]), "=r"(r[2]), "=r"(r[3]) : "r"(a));
}
__device__ __forceinline__ void mma16816(float (&c)[4], const uint32_t (&a)[4],
                                         uint32_t b0, uint32_t b1) {
    asm volatile(
        "mma.sync.aligned.m16n8k16.row.col.f32.f16.f16.f32 "
        "{%0,%1,%2,%3},{%4,%5,%6,%7},{%8,%9},{%0,%1,%2,%3};"
        : "+f"(c[0]), "+f"(c[1]), "+f"(c[2]), "+f"(c[3])
        : "r"(a[0]), "r"(a[1]), "r"(a[2]), "r"(a[3]), "r"(b0), "r"(b1));
}
__device__ __forceinline__ uint32_t h2u(__half2 h) {
    return *reinterpret_cast<uint32_t*>(&h);
}

// ---------------- P0 fused: convert H->fp16 + row sums + u = dv*(x@weight) ----------------
// Monolithic: grid 2048 x 256 threads; warp owns one row; 8 LDG.128 in flight per iter.
__global__ __launch_bounds__(256) void k_p0f(const float* __restrict__ H,
                                             const float* __restrict__ x,
                                             const float* __restrict__ w) {
    __shared__ float s_w[64][66];  // [k][f], pad 66 -> conflict-free column reads
    const int t = threadIdx.x;
    const int lane = t & 31;
    const int wid = t >> 5;
    for (int i = t; i < 4096; i += 256) s_w[i >> 6][i & 63] = w[i];

    const int row = blockIdx.x * 8 + wid;
    float2 xv = *(const float2*)&x[(size_t)row * 64 + 2 * lane];
    __syncthreads();

    const float4* __restrict__ src = (const float4*)(H + (size_t)row * EE);
    uint4* __restrict__ dst = (uint4*)(g_Hh + (size_t)row * EE);
    float s = 0.f;
    for (int j = 0; j < 8; j++) {
        const int base = j * 256;  // float4 units
        float4 v[8];
#pragma unroll
        for (int i = 0; i < 4; i++) {
            v[2 * i]     = src[base + i * 64 + 2 * lane];
            v[2 * i + 1] = src[base + i * 64 + 2 * lane + 1];
        }
#pragma unroll
        for (int i = 0; i < 4; i++) {
            float4 a = v[2 * i], b = v[2 * i + 1];
            uint4 uu;
            uu.x = h2u(__floats2half2_rn(a.x, a.y));
            uu.y = h2u(__floats2half2_rn(a.z, a.w));
            uu.z = h2u(__floats2half2_rn(b.x, b.y));
            uu.w = h2u(__floats2half2_rn(b.z, b.w));
            dst[j * 128 + i * 32 + lane] = uu;
            s += ((a.x + a.y) + (a.z + a.w)) + ((b.x + b.y) + (b.z + b.w));
        }
    }
#pragma unroll
    for (int o = 16; o; o >>= 1) s += __shfl_xor_sync(0xffffffffu, s, o);
    float dvn = rsqrtf(s);
    if (lane == 0) g_dv[row] = dvn;

    float a0 = 0.f, a1 = 0.f;
#pragma unroll
    for (int k = 0; k < 64; k++) {
        float xk = __shfl_sync(0xffffffffu, (k & 1) ? xv.y : xv.x, k >> 1);
        a0 += xk * s_w[k][lane];
        a1 += xk * s_w[k][lane + 32];
    }
    g_u[(size_t)row * 64 + lane] = __float2half_rn(dvn * a0);
    g_u[(size_t)row * 64 + lane + 32] = __float2half_rn(dvn * a1);
}

// ---------------- GEMM1: tpart[split] = H^T @ u over 1/SPLIT of n, plus col sums ----------------
// grid (EE/128, SPLIT) = (64, 8) = 512 CTAs; launch_bounds(256,4) -> 4 CTAs/SM.
// BM=128 (e), BN=64 (f), BK=32 (n), 3-stage.
#define G1_STAGES 3
__global__ __launch_bounds__(256, 4) void k_gemm1() {
    __shared__ __half sA[G1_STAGES][32][136];  // [k=n][m=e], stride 272B == 16 mod 128
    __shared__ __half sB[G1_STAGES][32][72];   // [k=n][f],  stride 144B == 16 mod 128
    __shared__ float2 s_red[256];
    const int t = threadIdx.x;
    const int lane = t & 31;
    const int wid = t >> 5;
    const int mb = (wid >> 1) * 32;
    const int nb = (wid & 1) * 32;
    const int e0 = blockIdx.x * 128;
    const size_t kbase = (size_t)blockIdx.y * (NN / SPLIT);
    float c[2][4][4];
#pragma unroll
    for (int i = 0; i < 2; i++)
#pragma unroll
        for (int j = 0; j < 4; j++)
#pragma unroll
            for (int k = 0; k < 4; k++) c[i][j][k] = 0.f;

    const int br = t >> 3, bc = (t & 7) * 8;
    const int cp2 = (t & 63) * 2;
    const int kr0 = (t >> 6) * 8;
    float csx = 0.f, csy = 0.f;

    const int ITERS = (NN / SPLIT) / 32;  // 64

#pragma unroll
    for (int s = 0; s < G1_STAGES - 1; s++) {
        size_t k0 = kbase + (size_t)s * 32;
#pragma unroll
        for (int i = 0; i < 2; i++) {
            int q = t + 256 * i, row = q >> 4, co = (q & 15) * 8;
            cp16(&sA[s][row][co], g_Hh + (k0 + row) * (size_t)EE + e0 + co);
        }
        cp16(&sB[s][br][bc], g_u + (k0 + br) * 64 + bc);
        cp_commit();
    }

    for (int it = 0; it < ITERS; ++it) {
        cp_wait<G1_STAGES - 2>();
        __syncthreads();
        const int cur = it % G1_STAGES;
        if (it + G1_STAGES - 1 < ITERS) {
            const int nxt = (it + G1_STAGES - 1) % G1_STAGES;
            size_t k0 = kbase + (size_t)(it + G1_STAGES - 1) * 32;
#pragma unroll
            for (int i = 0; i < 2; i++) {
                int q = t + 256 * i, row = q >> 4, co = (q & 15) * 8;
                cp16(&sA[nxt][row][co], g_Hh + (k0 + row) * (size_t)EE + e0 + co);
            }
            cp16(&sB[nxt][br][bc], g_u + (k0 + br) * 64 + bc);
        }
        cp_commit();
#pragma unroll
        for (int ks = 0; ks < 2; ks++) {
            const int kb = ks * 16;
            uint32_t a[2][4], b[2][4];
            {
                int krow = kb + (lane & 7) + ((lane & 16) ? 8 : 0);
                int mc0 = mb + ((lane & 8) ? 8 : 0);
                ldsm4t(a[0], &sA[cur][krow][mc0]);
                ldsm4t(a[1], &sA[cur][krow][mc0 + 16]);
            }
            {
                int krow = kb + (lane & 7) + (lane & 8);
                int nc0 = nb + ((lane & 16) ? 8 : 0);
                ldsm4t(b[0], &sB[cur][krow][nc0]);
                ldsm4t(b[1], &sB[cur][krow][nc0 + 16]);
            }
#pragma unroll
            for (int mi = 0; mi < 2; mi++)
#pragma unroll
                for (int nj = 0; nj < 2; nj++) {
                    mma16816(c[mi][2 * nj], a[mi], b[nj][0], b[nj][1]);
                    mma16816(c[mi][2 * nj + 1], a[mi], b[nj][2], b[nj][3]);
                }
        }
#pragma unroll
        for (int kk = 0; kk < 8; kk++) {
            __half2 v = *(const __half2*)&sA[cur][kr0 + kk][cp2];
            float2 f = __half22float2(v);
            csx += f.x;
            csy += f.y;
        }
    }

    s_red[t] = make_float2(csx, csy);
    __syncthreads();
    if (t < 64) {
        float2 a0 = s_red[t], a1 = s_red[t + 64], a2 = s_red[t + 128], a3 = s_red[t + 192];
        float2 r = make_float2(a0.x + a1.x + a2.x + a3.x, a0.y + a1.y + a2.y + a3.y);
        *(float2*)&g_departB[(size_t)blockIdx.y * EE + e0 + 2 * t] = r;
    }

    const int g = lane >> 2, tig = lane & 3;
    __half* op = g_tparth + (size_t)blockIdx.y * (EE * 64);
#pragma unroll
    for (int mi = 0; mi < 2; mi++) {
        int e = e0 + mb + mi * 16 + g;
#pragma unroll
        for (int nt = 0; nt < 4; nt++) {
            int f = nb + nt * 8 + 2 * tig;
            *(__half2*)&op[(size_t)e * 64 + f] = __floats2half2_rn(c[mi][nt][0], c[mi][nt][1]);
            *(__half2*)&op[(size_t)(e + 8) * 64 + f] = __floats2half2_rn(c[mi][nt][2], c[mi][nt][3]);
        }
    }
}

// ---------------- P3: t2 = fp16( se[e] * sum_s tpart[s] ),  se = W*2^14/colsum ----------------
__global__ __launch_bounds__(256) void k_combine(const float* __restrict__ W) {
    int idx = blockIdx.x * 256 + threadIdx.x;  // uint2 (4-half) index, 0 .. EE*16-1
    int e = idx >> 4;
    float cs = 0.f;
#pragma unroll
    for (int s = 0; s < SPLIT; s++) cs += g_departB[(size_t)s * EE + e];
    float se = W[e] * 16384.0f / cs;
    const uint2* tp = (const uint2*)g_tparth;
    float ax = 0.f, ay = 0.f, az = 0.f, aw = 0.f;
#pragma unroll
    for (int s = 0; s < SPLIT; s++) {
        uint2 v = tp[(size_t)s * (EE * 16) + idx];
        float2 f0 = __half22float2(*reinterpret_cast<__half2*>(&v.x));
        float2 f1 = __half22float2(*reinterpret_cast<__half2*>(&v.y));
        ax += f0.x; ay += f0.y; az += f1.x; aw += f1.y;
    }
    uint2 uu;
    uu.x = h2u(__floats2half2_rn(se * ax, se * ay));
    uu.y = h2u(__floats2half2_rn(se * az, se * aw));
    ((uint2*)g_t2)[idx] = uu;
}

// ---------------- GEMM2: oparth[split] = H @ t2 over 1/KSPLIT2 of e (fp16 partials) -------------
// grid (NN/128, KSPLIT2) = (128, 8) = 1024 CTAs;
// 256 threads (8 warps: 4m x 2n, 32x32 warp tiles); BM=128, BN=64, BK=32, 3-stage.
#define G2_STAGES 3
__global__ __launch_bounds__(256, 4) void k_gemm2() {
    __shared__ __half sA[G2_STAGES][128][40];  // [m=n][k=e], stride 80B
    __shared__ __half sB[G2_STAGES][32][72];   // [k=e][f]
    const int t = threadIdx.x;
    const int lane = t & 31;
    const int wid = t >> 5;
    const int mb = (wid >> 1) * 32;   // 4 m-warps
    const int nb = (wid & 1) * 32;    // 2 n-warps
    const int m0 = blockIdx.x * 128;
    const size_t kbase = (size_t)blockIdx.y * (EE / KSPLIT2);
    float c[2][4][4];
#pragma unroll
    for (int i = 0; i < 2; i++)
#pragma unroll
        for (int j = 0; j < 4; j++)
#pragma unroll
            for (int k = 0; k < 4; k++) c[i][j][k] = 0.f;

    const int br = t >> 3, bc = (t & 7) * 8;
    const int ITERS = (EE / KSPLIT2) / 32;  // 32

#pragma unroll
    for (int s = 0; s < G2_STAGES - 1; s++) {
        size_t k0 = kbase + (size_t)s * 32;
#pragma unroll
        for (int i = 0; i < 2; i++) {
            int q = t + 256 * i, row = q >> 2, co = (q & 3) * 8;
            cp16(&sA[s][row][co], g_Hh + (size_t)(m0 + row) * EE + k0 + co);
        }
        cp16(&sB[s][br][bc], g_t2 + (k0 + br) * 64 + bc);
        cp_commit();
    }

    for (int it = 0; it < ITERS; ++it) {
        cp_wait<G2_STAGES - 2>();
        __syncthreads();
        const int cur = it % G2_STAGES;
        if (it + G2_STAGES - 1 < ITERS) {
            const int nxt = (it + G2_STAGES - 1) % G2_STAGES;
            size_t k0 = kbase + (size_t)(it + G2_STAGES - 1) * 32;
#pragma unroll
            for (int i = 0; i < 2; i++) {
                int q = t + 256 * i, row = q >> 2, co = (q & 3) * 8;
                cp16(&sA[nxt][row][co], g_Hh + (size_t)(m0 + row) * EE + k0 + co);
            }
            cp16(&sB[nxt][br][bc], g_t2 + (k0 + br) * 64 + bc);
        }
        cp_commit();
#pragma unroll
        for (int ks = 0; ks < 2; ks++) {
            const int kb = ks * 16;
            uint32_t a[2][4], b[2][4];
            {
                int arow = mb + (lane & 15);
                int kc = kb + ((lane & 16) ? 8 : 0);
                ldsm4(a[0], &sA[cur][arow][kc]);
                ldsm4(a[1], &sA[cur][arow + 16][kc]);
            }
            {
                int krow = kb + (lane & 7) + (lane & 8);
                int nc0 = nb + ((lane & 16) ? 8 : 0);
                ldsm4t(b[0], &sB[cur][krow][nc0]);
                ldsm4t(b[1], &sB[cur][krow][nc0 + 16]);
            }
#pragma unroll
            for (int mi = 0; mi < 2; mi++)
#pragma unroll
                for (int nj = 0; nj < 2; nj++) {
                    mma16816(c[mi][2 * nj], a[mi], b[nj][0], b[nj][1]);
                    mma16816(c[mi][2 * nj + 1], a[mi], b[nj][2], b[nj][3]);
                }
        }
    }

    const int g = lane >> 2, tig = lane & 3;
    __half* op = g_oparth + (size_t)blockIdx.y * ((size_t)NN * 64);
#pragma unroll
    for (int mi = 0; mi < 2; mi++) {
        int n = m0 + mb + mi * 16 + g;
#pragma unroll
        for (int nt = 0; nt < 4; nt++) {
            int f = nb + nt * 8 + 2 * tig;
            *(__half2*)&op[(size_t)n * 64 + f] = __floats2half2_rn(c[mi][nt][0], c[mi][nt][1]);
            *(__half2*)&op[(size_t)(n + 8) * 64 + f] = __floats2half2_rn(c[mi][nt][2], c[mi][nt][3]);
        }
    }
}

// ---------------- Epilogue: out = dv * (sum of fp16 partials) / 2^14 + bias ----------------
__global__ __launch_bounds__(256) void k_epi(const float* __restrict__ bias,
                                             float* __restrict__ out) {
    int idx = blockIdx.x * 256 + threadIdx.x;  // uint2 (4-half) index, 0 .. NN*16-1
    int n = idx >> 4;
    float dvn = g_dv[n] * OUT_SCALE;
    const uint2* p = (const uint2*)g_oparth;
    float ax = 0.f, ay = 0.f, az = 0.f, aw = 0.f;
#pragma unroll
    for (int s = 0; s < KSPLIT2; s++) {
        uint2 v = p[(size_t)s * (NN * 16) + idx];
        float2 f0 = __half22float2(*reinterpret_cast<__half2*>(&v.x));
        float2 f1 = __half22float2(*reinterpret_cast<__half2*>(&v.y));
        ax += f0.x; ay += f0.y; az += f1.x; aw += f1.y;
    }
    int f = (idx & 15) * 4;
    float4 r;
    r.x = dvn * ax + bias[f];
    r.y = dvn * ay + bias[f + 1];
    r.z = dvn * az + bias[f + 2];
    r.w = dvn * aw + bias[f + 3];
    ((float4*)out)[idx] = r;
}

// ---------------- launch ----------------
extern "C" void kernel_launch(void* const* d_in, const int* in_sizes, int n_in,
                              void* d_out, int out_size) {
    (void)in_sizes; (void)n_in; (void)out_size;
    const float* x = (const float*)d_in[0];       // [N,64]
    const float* H = (const float*)d_in[1];       // [N,E]
    const float* W = (const float*)d_in[2];       // [E]
    const float* w = (const float*)d_in[3];       // [64,64]
    const float* b = (const float*)d_in[4];       // [64]
    float* out = (float*)d_out;                   // [N,64]

    k_p0f<<<2048, 256>>>(H, x, w);
    k_gemm1<<<dim3(64, SPLIT), 256>>>();
    k_combine<<<512, 256>>>(W);
    k_gemm2<<<dim3(128, KSPLIT2), 256>>>();
    k_epi<<<1024, 256>>>(b, out);
}